// round 2
// baseline (speedup 1.0000x reference)
#include <cuda_runtime.h>
#include <math.h>

#define VOCAB  50000
#define BATCH  1024
#define SEQ    120
#define EMBED  50
#define HIDDEN 300
#define NCLASS 5
#define GATES  1200   // 4*HIDDEN, packed as col' = 4*hh + gate (i,j,f,o)

// Scratch (allocation-free rule: __device__ globals)
__device__ float EW_buf[(size_t)VOCAB * GATES];          // 240 MB: emb @ Wx + b, packed cols
__device__ float Whp_buf[HIDDEN * GATES];                // packed recurrent weights
__device__ float Hall_buf[(size_t)SEQ * BATCH * HIDDEN]; // all hidden states
__device__ float C_buf[BATCH * HIDDEN];                  // cell state

__device__ __forceinline__ float sigf(float x) { return 1.0f / (1.0f + expf(-x)); }

// ---------------------------------------------------------------------------
// EW[v][col'] = b_lstm[orig(col')] + sum_e emb[v][e] * W[e][orig(col')]
// orig(col') = (col' & 3) * HIDDEN + (col' >> 2)
// Tiled GEMM M=50000, N=1200, K=50 (full K in smem)
// ---------------------------------------------------------------------------
__global__ __launch_bounds__(256) void ew_kernel(const float* __restrict__ emb,
                                                 const float* __restrict__ W,
                                                 const float* __restrict__ bl) {
    __shared__ float As[64][EMBED];     // [row][k]
    __shared__ float Bs[EMBED][68];     // [k][col], padded

    int tx = threadIdx.x & 15, ty = threadIdx.x >> 4;
    int rowBase = blockIdx.y * 64;
    int colBase = blockIdx.x * 64;

    for (int idx = threadIdx.x; idx < 64 * EMBED; idx += 256) {
        int r = idx / EMBED, k = idx % EMBED;
        int v = rowBase + r;
        As[r][k] = (v < VOCAB) ? emb[(size_t)v * EMBED + k] : 0.f;
    }
    for (int idx = threadIdx.x; idx < EMBED * 64; idx += 256) {
        int k = idx >> 6, c = idx & 63;
        int col = colBase + c;
        float val = 0.f;
        if (col < GATES) {
            int g = col & 3, hh = col >> 2;
            val = W[(size_t)k * GATES + g * HIDDEN + hh];
        }
        Bs[k][c] = val;
    }
    __syncthreads();

    float acc[4][4] = {};
    #pragma unroll 5
    for (int k = 0; k < EMBED; k++) {
        float a[4], b[4];
        #pragma unroll
        for (int i = 0; i < 4; i++) a[i] = As[ty * 4 + i][k];
        #pragma unroll
        for (int j = 0; j < 4; j++) b[j] = Bs[k][tx * 4 + j];
        #pragma unroll
        for (int i = 0; i < 4; i++)
            #pragma unroll
            for (int j = 0; j < 4; j++) acc[i][j] += a[i] * b[j];
    }

    #pragma unroll
    for (int j = 0; j < 4; j++) {
        int col = colBase + tx * 4 + j;
        if (col >= GATES) continue;
        int g = col & 3, hh = col >> 2;
        float bias = bl[g * HIDDEN + hh];
        #pragma unroll
        for (int i = 0; i < 4; i++) {
            int v = rowBase + ty * 4 + i;
            if (v < VOCAB) EW_buf[(size_t)v * GATES + col] = acc[i][j] + bias;
        }
    }
}

// ---------------------------------------------------------------------------
// Whp[k][col'] = W[EMBED + k][orig(col')]
// ---------------------------------------------------------------------------
__global__ void pack_wh(const float* __restrict__ W) {
    int idx = blockIdx.x * 256 + threadIdx.x;
    if (idx < HIDDEN * GATES) {
        int c = idx % GATES;
        int k = idx / GATES;
        int g = c & 3, hh = c >> 2;
        Whp_buf[idx] = W[(size_t)(EMBED + k) * GATES + g * HIDDEN + hh];
    }
}

// ---------------------------------------------------------------------------
// One LSTM step: z = EW[id] + h_{t-1} @ Whp, then fused gate update.
// GEMM M=1024, N=1200, K=300. BM=BN=64, BK=16, 4x4 microtile, 256 threads.
// Each thread's 4 columns are the complete (i,j,f,o) group of one hidden unit.
// ---------------------------------------------------------------------------
__global__ __launch_bounds__(256) void step_kernel(int t, const int* __restrict__ ids) {
    __shared__ float As[16][68];   // [k][row]
    __shared__ float Bs[16][68];   // [k][col]

    int tx = threadIdx.x & 15, ty = threadIdx.x >> 4;
    int rowBase = blockIdx.y * 64;
    int colBase = blockIdx.x * 64;

    float acc[4][4] = {};

    if (t > 0) {
        const float* hprev = &Hall_buf[(size_t)(t - 1) * BATCH * HIDDEN];
        for (int kk = 0; kk < HIDDEN; kk += 16) {
            int kmax = HIDDEN - kk;  // >=16 except last (12)
            // A: h rows, coalesced-in-k load, store transposed
            for (int idx = threadIdx.x; idx < 64 * 16; idx += 256) {
                int k = idx & 15, r = idx >> 4;
                As[k][r] = (k < kmax) ? hprev[(size_t)(rowBase + r) * HIDDEN + kk + k] : 0.f;
            }
            // B: packed weights, fully coalesced
            for (int idx = threadIdx.x; idx < 16 * 64; idx += 256) {
                int c = idx & 63, k = idx >> 6;
                int col = colBase + c;
                Bs[k][c] = (k < kmax && col < GATES)
                               ? Whp_buf[(size_t)(kk + k) * GATES + col] : 0.f;
            }
            __syncthreads();
            #pragma unroll
            for (int k = 0; k < 16; k++) {
                float a[4], b[4];
                #pragma unroll
                for (int i = 0; i < 4; i++) a[i] = As[k][ty * 4 + i];
                #pragma unroll
                for (int j = 0; j < 4; j++) b[j] = Bs[k][tx * 4 + j];
                #pragma unroll
                for (int i = 0; i < 4; i++)
                    #pragma unroll
                    for (int j = 0; j < 4; j++) acc[i][j] += a[i] * b[j];
            }
            __syncthreads();
        }
    }

    int col0 = colBase + tx * 4;          // multiple of 4 -> one full gate group
    if (col0 < GATES) {
        int hh = col0 >> 2;
        #pragma unroll
        for (int i = 0; i < 4; i++) {
            int b = rowBase + ty * 4 + i;
            int id = ids[b * SEQ + t];    // input_ids[b][t][0]
            const float* ew = &EW_buf[(size_t)id * GATES + col0];
            float zi = acc[i][0] + ew[0];
            float zj = acc[i][1] + ew[1];
            float zf = acc[i][2] + ew[2];
            float zo = acc[i][3] + ew[3];
            float cprev = (t == 0) ? 0.f : C_buf[b * HIDDEN + hh];
            float cn = cprev * sigf(zf + 1.0f) + sigf(zi) * tanhf(zj);
            float hn = tanhf(cn) * sigf(zo);
            C_buf[b * HIDDEN + hh] = cn;
            Hall_buf[((size_t)t * BATCH + b) * HIDDEN + hh] = hn;
        }
    }
}

// ---------------------------------------------------------------------------
// out[t][b][k] = h_t[b] @ U + b2 ; rows = T*B, tiled 32 rows/block
// ---------------------------------------------------------------------------
__global__ __launch_bounds__(160) void proj_kernel(const float* __restrict__ U,
                                                   const float* __restrict__ b2,
                                                   float* __restrict__ out) {
    __shared__ float Hs[32 * HIDDEN];
    __shared__ float Us[HIDDEN * NCLASS];
    __shared__ float b2s[NCLASS];

    size_t rowBase = (size_t)blockIdx.x * 32;
    for (int idx = threadIdx.x; idx < 32 * HIDDEN; idx += 160)
        Hs[idx] = Hall_buf[rowBase * HIDDEN + idx];
    for (int idx = threadIdx.x; idx < HIDDEN * NCLASS; idx += 160)
        Us[idx] = U[idx];
    if (threadIdx.x < NCLASS) b2s[threadIdx.x] = b2[threadIdx.x];
    __syncthreads();

    int r = threadIdx.x / NCLASS, k = threadIdx.x % NCLASS;
    float acc = 0.f;
    #pragma unroll 4
    for (int hh = 0; hh < HIDDEN; hh++)
        acc += Hs[r * HIDDEN + hh] * Us[hh * NCLASS + k];
    out[(rowBase + r) * NCLASS + k] = acc + b2s[k];
}

// ---------------------------------------------------------------------------
extern "C" void kernel_launch(void* const* d_in, const int* in_sizes, int n_in,
                              void* d_out, int out_size) {
    const int*   ids = (const int*)d_in[0];     // (1024,120,1) int32
    const float* emb = (const float*)d_in[1];   // (50000,50)
    const float* W   = (const float*)d_in[2];   // (350,1200)
    const float* bl  = (const float*)d_in[3];   // (1200)
    const float* U   = (const float*)d_in[4];   // (300,5)
    const float* b2  = (const float*)d_in[5];   // (5)
    float* out = (float*)d_out;                 // (120,1024,5)

    dim3 ewgrid((GATES + 63) / 64, (VOCAB + 63) / 64);
    ew_kernel<<<ewgrid, 256>>>(emb, W, bl);
    pack_wh<<<(HIDDEN * GATES + 255) / 256, 256>>>(W);

    dim3 sgrid((GATES + 63) / 64, BATCH / 64);
    for (int t = 0; t < SEQ; t++)
        step_kernel<<<sgrid, 256>>>(t, ids);

    proj_kernel<<<(SEQ * BATCH) / 32, 160>>>(U, b2, out);
}

// round 4
// speedup vs baseline: 1.6952x; 1.6952x over previous
#include <cuda_runtime.h>
#include <math.h>

#define VOCAB  50000
#define BATCH  1024
#define SEQ    120
#define EMBED  50
#define HIDDEN 300
#define NCLASS 5
#define GATES  1200   // 4*HIDDEN, packed as col' = 4*hh + gate (i,j,f,o)

#define NBLK    152   // 8 M-tiles (128 rows) x 19 N-tiles (64 cols)
#define BK      30
#define ASTRIDE 132   // 128 + 4 pad, keeps 16B alignment of row groups
#define SMEM_B_FLOATS (HIDDEN * 64)            // 19200
#define SMEM_A_FLOATS (2 * BK * ASTRIDE)       // 7920
#define SMEM_BYTES ((SMEM_B_FLOATS + SMEM_A_FLOATS) * 4)  // 108480

typedef unsigned long long u64;

// Scratch (allocation-free rule: __device__ globals)
__device__ float EW_buf[(size_t)VOCAB * GATES];          // emb @ Wx + b, packed cols
__device__ float Whp_buf[HIDDEN * GATES];                // packed recurrent weights
__device__ float Hall_buf[(size_t)SEQ * BATCH * HIDDEN]; // all hidden states
__device__ float C_buf[BATCH * HIDDEN];                  // cell state

// grid barrier state (returns to arrive=0 after every barrier; gen monotonic)
__device__ unsigned gbar_arrive;
__device__ volatile unsigned gbar_gen;

__device__ __forceinline__ float sigf(float x) { return 1.0f / (1.0f + expf(-x)); }

__device__ __forceinline__ u64 pack2(float lo, float hi) {
    u64 r; asm("mov.b64 %0, {%1, %2};" : "=l"(r) : "f"(lo), "f"(hi)); return r;
}
__device__ __forceinline__ void unpack2(u64 v, float& lo, float& hi) {
    asm("mov.b64 {%0, %1}, %2;" : "=f"(lo), "=f"(hi) : "l"(v));
}
__device__ __forceinline__ u64 ffma2(u64 a, u64 b, u64 c) {
    u64 d; asm("fma.rn.f32x2 %0, %1, %2, %3;" : "=l"(d) : "l"(a), "l"(b), "l"(c));
    return d;
}

// ---------------------------------------------------------------------------
// EW[v][col'] = b_lstm[orig(col')] + sum_e emb[v][e] * W[e][orig(col')]
// ---------------------------------------------------------------------------
__global__ __launch_bounds__(256) void ew_kernel(const float* __restrict__ emb,
                                                 const float* __restrict__ W,
                                                 const float* __restrict__ bl) {
    __shared__ float As[64][EMBED];
    __shared__ float Bs[EMBED][68];

    int tx = threadIdx.x & 15, ty = threadIdx.x >> 4;
    int rowBase = blockIdx.y * 64;
    int colBase = blockIdx.x * 64;

    for (int idx = threadIdx.x; idx < 64 * EMBED; idx += 256) {
        int r = idx / EMBED, k = idx % EMBED;
        int v = rowBase + r;
        As[r][k] = (v < VOCAB) ? emb[(size_t)v * EMBED + k] : 0.f;
    }
    for (int idx = threadIdx.x; idx < EMBED * 64; idx += 256) {
        int k = idx >> 6, c = idx & 63;
        int col = colBase + c;
        float val = 0.f;
        if (col < GATES) {
            int g = col & 3, hh = col >> 2;
            val = W[(size_t)k * GATES + g * HIDDEN + hh];
        }
        Bs[k][c] = val;
    }
    __syncthreads();

    float acc[4][4] = {};
    #pragma unroll 5
    for (int k = 0; k < EMBED; k++) {
        float a[4], b[4];
        #pragma unroll
        for (int i = 0; i < 4; i++) a[i] = As[ty * 4 + i][k];
        #pragma unroll
        for (int j = 0; j < 4; j++) b[j] = Bs[k][tx * 4 + j];
        #pragma unroll
        for (int i = 0; i < 4; i++)
            #pragma unroll
            for (int j = 0; j < 4; j++) acc[i][j] += a[i] * b[j];
    }

    #pragma unroll
    for (int j = 0; j < 4; j++) {
        int col = colBase + tx * 4 + j;
        if (col >= GATES) continue;
        int g = col & 3, hh = col >> 2;
        float bias = bl[g * HIDDEN + hh];
        #pragma unroll
        for (int i = 0; i < 4; i++) {
            int v = rowBase + ty * 4 + i;
            if (v < VOCAB) EW_buf[(size_t)v * GATES + col] = acc[i][j] + bias;
        }
    }
}

__global__ void pack_wh(const float* __restrict__ W) {
    int idx = blockIdx.x * 256 + threadIdx.x;
    if (idx < HIDDEN * GATES) {
        int c = idx % GATES;
        int k = idx / GATES;
        int g = c & 3, hh = c >> 2;
        Whp_buf[idx] = W[(size_t)(EMBED + k) * GATES + g * HIDDEN + hh];
    }
}

// ---------------------------------------------------------------------------
// Persistent LSTM scan. One block = one fixed (128-row, 64-col) output tile
// for all 120 steps. B tile (Whp slice) stays resident in smem. A tile
// (h_prev) is double-buffered with BK=30. 4 packed cols = one (i,j,f,o)
// group -> fused gate epilogue. Grid-wide barrier between steps.
// ---------------------------------------------------------------------------
__global__ __launch_bounds__(256, 2) void lstm_persist(const int* __restrict__ ids) {
    extern __shared__ float smem_dyn[];
    float* Bsr = smem_dyn;                  // [300][64]
    float* As  = smem_dyn + SMEM_B_FLOATS;  // [2][BK][ASTRIDE]

    const int tid = threadIdx.x;
    const int tx = tid & 15, ty = tid >> 4;
    const int mt = blockIdx.x % 8, nt = blockIdx.x / 8;
    const int rowBase = mt * 128;
    const int colBase = nt * 64;
    const int col0 = colBase + tx * 4;
    const int hh = col0 >> 2;
    const int rb = rowBase + ty * 8;   // this thread's first batch row

    // Load resident B slice (zero-pad OOB cols of the last tile)
    for (int idx = tid; idx < HIDDEN * 64; idx += 256) {
        int k = idx >> 6, c = idx & 63;
        int col = colBase + c;
        Bsr[idx] = (col < GATES) ? Whp_buf[(size_t)k * GATES + col] : 0.f;
    }
    __syncthreads();

    for (int t = 0; t < SEQ; t++) {
        u64 acc2[4][4];
        #pragma unroll
        for (int i = 0; i < 4; i++)
            #pragma unroll
            for (int j = 0; j < 4; j++) acc2[i][j] = 0ull;

        if (t > 0) {
            const float* hprev = &Hall_buf[(size_t)(t - 1) * BATCH * HIDDEN + (size_t)rowBase * HIDDEN];
            float stage[15];

            // prologue: chunk 0 -> buffer 0
            #pragma unroll
            for (int j = 0; j < 15; j++) {
                int idx = tid + j * 256;
                int r = idx / BK, k = idx % BK;
                stage[j] = hprev[(size_t)r * HIDDEN + k];
            }
            #pragma unroll
            for (int j = 0; j < 15; j++) {
                int idx = tid + j * 256;
                int r = idx / BK, k = idx % BK;
                As[k * ASTRIDE + r] = stage[j];
            }
            __syncthreads();

            for (int c = 0; c < HIDDEN / BK; c++) {
                int kk = c * BK;
                if (c < HIDDEN / BK - 1) {
                    #pragma unroll
                    for (int j = 0; j < 15; j++) {
                        int idx = tid + j * 256;
                        int r = idx / BK, k = idx % BK;
                        stage[j] = hprev[(size_t)r * HIDDEN + kk + BK + k];
                    }
                }
                const float* Acur = &As[(c & 1) * BK * ASTRIDE];
                #pragma unroll 3
                for (int k = 0; k < BK; k++) {
                    ulonglong2 A0 = *(const ulonglong2*)&Acur[k * ASTRIDE + ty * 8];
                    ulonglong2 A1 = *(const ulonglong2*)&Acur[k * ASTRIDE + ty * 8 + 4];
                    float4 b4 = *(const float4*)&Bsr[(kk + k) * 64 + tx * 4];
                    u64 bd0 = pack2(b4.x, b4.x);
                    u64 bd1 = pack2(b4.y, b4.y);
                    u64 bd2 = pack2(b4.z, b4.z);
                    u64 bd3 = pack2(b4.w, b4.w);
                    u64 ap0 = A0.x, ap1 = A0.y, ap2 = A1.x, ap3 = A1.y;
                    acc2[0][0] = ffma2(ap0, bd0, acc2[0][0]);
                    acc2[0][1] = ffma2(ap0, bd1, acc2[0][1]);
                    acc2[0][2] = ffma2(ap0, bd2, acc2[0][2]);
                    acc2[0][3] = ffma2(ap0, bd3, acc2[0][3]);
                    acc2[1][0] = ffma2(ap1, bd0, acc2[1][0]);
                    acc2[1][1] = ffma2(ap1, bd1, acc2[1][1]);
                    acc2[1][2] = ffma2(ap1, bd2, acc2[1][2]);
                    acc2[1][3] = ffma2(ap1, bd3, acc2[1][3]);
                    acc2[2][0] = ffma2(ap2, bd0, acc2[2][0]);
                    acc2[2][1] = ffma2(ap2, bd1, acc2[2][1]);
                    acc2[2][2] = ffma2(ap2, bd2, acc2[2][2]);
                    acc2[2][3] = ffma2(ap2, bd3, acc2[2][3]);
                    acc2[3][0] = ffma2(ap3, bd0, acc2[3][0]);
                    acc2[3][1] = ffma2(ap3, bd1, acc2[3][1]);
                    acc2[3][2] = ffma2(ap3, bd2, acc2[3][2]);
                    acc2[3][3] = ffma2(ap3, bd3, acc2[3][3]);
                }
                if (c < HIDDEN / BK - 1) {
                    float* Anext = &As[((c + 1) & 1) * BK * ASTRIDE];
                    #pragma unroll
                    for (int j = 0; j < 15; j++) {
                        int idx = tid + j * 256;
                        int r = idx / BK, k = idx % BK;
                        Anext[k * ASTRIDE + r] = stage[j];
                    }
                }
                __syncthreads();
            }
        }

        // Fused gate epilogue: 4 packed cols per thread = (i,j,f,o) of unit hh
        if (col0 < GATES) {
            #pragma unroll
            for (int rp = 0; rp < 4; rp++) {
                float z0[4], z1[4];
                #pragma unroll
                for (int j = 0; j < 4; j++) unpack2(acc2[rp][j], z0[j], z1[j]);
                #pragma unroll
                for (int half = 0; half < 2; half++) {
                    float* z = half ? z1 : z0;
                    int b = rb + rp * 2 + half;
                    int id = ids[b * SEQ + t];
                    float4 ew = *(const float4*)&EW_buf[(size_t)id * GATES + col0];
                    float zi = z[0] + ew.x;
                    float zj = z[1] + ew.y;
                    float zf = z[2] + ew.z;
                    float zo = z[3] + ew.w;
                    float cprev = (t == 0) ? 0.f : C_buf[b * HIDDEN + hh];
                    float cn = cprev * sigf(zf + 1.0f) + sigf(zi) * tanhf(zj);
                    float hn = tanhf(cn) * sigf(zo);
                    C_buf[b * HIDDEN + hh] = cn;
                    Hall_buf[((size_t)t * BATCH + b) * HIDDEN + hh] = hn;
                }
            }
        }

        // grid-wide barrier (all 152 blocks co-resident by construction)
        if (t < SEQ - 1) {
            __threadfence();
            __syncthreads();
            if (tid == 0) {
                unsigned gen = gbar_gen;
                if (atomicAdd(&gbar_arrive, 1u) == NBLK - 1) {
                    gbar_arrive = 0;
                    __threadfence();
                    gbar_gen = gen + 1;
                } else {
                    while (gbar_gen == gen) __nanosleep(64);
                }
                __threadfence();
            }
            __syncthreads();
        }
    }
}

// ---------------------------------------------------------------------------
// out[t][b][k] = h_t[b] @ U + b2
// ---------------------------------------------------------------------------
__global__ __launch_bounds__(160) void proj_kernel(const float* __restrict__ U,
                                                   const float* __restrict__ b2,
                                                   float* __restrict__ out) {
    __shared__ float Hs[32 * HIDDEN];
    __shared__ float Us[HIDDEN * NCLASS];
    __shared__ float b2s[NCLASS];

    size_t rowBase = (size_t)blockIdx.x * 32;
    for (int idx = threadIdx.x; idx < 32 * HIDDEN; idx += 160)
        Hs[idx] = Hall_buf[rowBase * HIDDEN + idx];
    for (int idx = threadIdx.x; idx < HIDDEN * NCLASS; idx += 160)
        Us[idx] = U[idx];
    if (threadIdx.x < NCLASS) b2s[threadIdx.x] = b2[threadIdx.x];
    __syncthreads();

    int r = threadIdx.x / NCLASS, k = threadIdx.x % NCLASS;
    float acc = 0.f;
    #pragma unroll 4
    for (int hh = 0; hh < HIDDEN; hh++)
        acc += Hs[r * HIDDEN + hh] * Us[hh * NCLASS + k];
    out[(rowBase + r) * NCLASS + k] = acc + b2s[k];
}

// ---------------------------------------------------------------------------
extern "C" void kernel_launch(void* const* d_in, const int* in_sizes, int n_in,
                              void* d_out, int out_size) {
    const int*   ids = (const int*)d_in[0];     // (1024,120,1) int32
    const float* emb = (const float*)d_in[1];   // (50000,50)
    const float* W   = (const float*)d_in[2];   // (350,1200)
    const float* bl  = (const float*)d_in[3];   // (1200)
    const float* U   = (const float*)d_in[4];   // (300,5)
    const float* b2  = (const float*)d_in[5];   // (5)
    float* out = (float*)d_out;                 // (120,1024,5)

    cudaFuncSetAttribute(lstm_persist,
                         cudaFuncAttributeMaxDynamicSharedMemorySize, SMEM_BYTES);

    dim3 ewgrid((GATES + 63) / 64, (VOCAB + 63) / 64);
    ew_kernel<<<ewgrid, 256>>>(emb, W, bl);
    pack_wh<<<(HIDDEN * GATES + 255) / 256, 256>>>(W);

    lstm_persist<<<NBLK, 256, SMEM_BYTES>>>(ids);

    proj_kernel<<<(SEQ * BATCH) / 32, 160>>>(U, b2, out);
}

// round 7
// speedup vs baseline: 1.8277x; 1.0782x over previous
#include <cuda_runtime.h>
#include <math.h>

#define VOCAB  50000
#define BATCH  1024
#define SEQ    120
#define EMBED  50
#define HIDDEN 300
#define NCLASS 5
#define GATES  1200   // 4*HIDDEN, packed as col' = 4*hh + gate (i,j,f,o)

#define MT 8
#define NT 18
#define NBLK (MT*NT)      // 144 blocks -> one per SM (148+ SMs)
#define BM 128
#define BN 68             // 16*4 main cols + 4 extra cols
#define BK 30
#define ASTRIDE 132       // 128 + 4 pad (16B-aligned row groups)

// dynamic smem layout (floats)
#define SM_B    (HIDDEN*BN)        // 20400 : resident Whp slice
#define SM_A    (2*BK*ASTRIDE)     // 7920  : double-buffered h tile
#define SM_IDS  (BM*SEQ)           // 15360 : token ids for this block's rows
#define SM_EXCH (4*BM)             // 512   : extra-col accumulator exchange
#define SM_TOT  (SM_B+SM_A+SM_IDS+SM_EXCH)       // 44192 floats
#define SMEM_BYTES (SM_TOT*4)                    // 176768 B (< 227KB/SM)

#define PROJ_ROWS 128
#define HSTRIDE 308
#define PROJ_SMEM ((PROJ_ROWS*HSTRIDE + HIDDEN*NCLASS + PROJ_ROWS*NCLASS + 8)*4)

typedef unsigned long long u64;

// Scratch (allocation-free rule: __device__ globals)
__device__ float EW_buf[(size_t)VOCAB * GATES];
__device__ float Whp_buf[HIDDEN * GATES];
__device__ float Hall_buf[(size_t)SEQ * BATCH * HIDDEN];
__device__ float C_buf[BATCH * HIDDEN];

// Per-M-tile barriers: block (mt,nt) only depends on the 18 blocks with the
// same mt (they produce all 300 h-columns of its batch rows). 8 independent
// groups of 18 -> no global coupling, decoupled stragglers.
__device__ unsigned bar_arrive[MT];
__device__ unsigned bar_gen[MT];

__device__ __forceinline__ unsigned ld_volatile_u32(unsigned* p) {
    unsigned v;
    asm volatile("ld.volatile.global.u32 %0, [%1];" : "=r"(v) : "l"(p));
    return v;
}

__device__ __forceinline__ float sigf(float x) { return 1.0f / (1.0f + expf(-x)); }

__device__ __forceinline__ u64 pack2(float lo, float hi) {
    u64 r; asm("mov.b64 %0, {%1, %2};" : "=l"(r) : "f"(lo), "f"(hi)); return r;
}
__device__ __forceinline__ void unpack2(u64 v, float& lo, float& hi) {
    asm("mov.b64 {%0, %1}, %2;" : "=f"(lo), "=f"(hi) : "l"(v));
}
__device__ __forceinline__ u64 ffma2(u64 a, u64 b, u64 c) {
    u64 d; asm("fma.rn.f32x2 %0, %1, %2, %3;" : "=l"(d) : "l"(a), "l"(b), "l"(c));
    return d;
}

// ---------------------------------------------------------------------------
// EW[v][col'] = b_lstm[orig(col')] + sum_e emb[v][e] * W[e][orig(col')]
// ---------------------------------------------------------------------------
__global__ __launch_bounds__(256) void ew_kernel(const float* __restrict__ emb,
                                                 const float* __restrict__ W,
                                                 const float* __restrict__ bl) {
    __shared__ float Ast[EMBED * 68];   // [k][row] 64 rows + pad
    __shared__ float Bs[EMBED * 68];    // [k][col] 64 cols + pad

    int tid = threadIdx.x;
    int tx = tid & 15, ty = tid >> 4;
    int rowBase = blockIdx.y * 64;
    int colBase = blockIdx.x * 64;

    for (int idx = tid; idx < 64 * EMBED; idx += 256) {
        int r = idx / EMBED, k = idx % EMBED;
        int v = rowBase + r;
        Ast[k * 68 + r] = (v < VOCAB) ? emb[(size_t)v * EMBED + k] : 0.f;
    }
    for (int idx = tid; idx < EMBED * 64; idx += 256) {
        int k = idx >> 6, c = idx & 63;
        int col = colBase + c;
        float val = 0.f;
        if (col < GATES) {
            int g = col & 3, hh = col >> 2;
            val = W[(size_t)k * GATES + g * HIDDEN + hh];
        }
        Bs[k * 68 + c] = val;
    }
    __syncthreads();

    u64 acc[2][4];
    #pragma unroll
    for (int p = 0; p < 2; p++)
        #pragma unroll
        for (int j = 0; j < 4; j++) acc[p][j] = 0ull;

    #pragma unroll 5
    for (int k = 0; k < EMBED; k++) {
        ulonglong2 A0 = *(const ulonglong2*)&Ast[k * 68 + ty * 4];
        float4 b4 = *(const float4*)&Bs[k * 68 + tx * 4];
        u64 bd0 = pack2(b4.x, b4.x), bd1 = pack2(b4.y, b4.y);
        u64 bd2 = pack2(b4.z, b4.z), bd3 = pack2(b4.w, b4.w);
        acc[0][0] = ffma2(A0.x, bd0, acc[0][0]);
        acc[0][1] = ffma2(A0.x, bd1, acc[0][1]);
        acc[0][2] = ffma2(A0.x, bd2, acc[0][2]);
        acc[0][3] = ffma2(A0.x, bd3, acc[0][3]);
        acc[1][0] = ffma2(A0.y, bd0, acc[1][0]);
        acc[1][1] = ffma2(A0.y, bd1, acc[1][1]);
        acc[1][2] = ffma2(A0.y, bd2, acc[1][2]);
        acc[1][3] = ffma2(A0.y, bd3, acc[1][3]);
    }

    int col0 = colBase + tx * 4;
    if (col0 < GATES) {
        int hh = col0 >> 2;
        float bias[4];
        #pragma unroll
        for (int j = 0; j < 4; j++) bias[j] = bl[j * HIDDEN + hh];
        #pragma unroll
        for (int p = 0; p < 2; p++) {
            float lo[4], hi[4];
            #pragma unroll
            for (int j = 0; j < 4; j++) unpack2(acc[p][j], lo[j], hi[j]);
            int v0 = rowBase + ty * 4 + p * 2;
            if (v0 < VOCAB) {
                float4 o = make_float4(lo[0] + bias[0], lo[1] + bias[1],
                                       lo[2] + bias[2], lo[3] + bias[3]);
                *(float4*)&EW_buf[(size_t)v0 * GATES + col0] = o;
            }
            if (v0 + 1 < VOCAB) {
                float4 o = make_float4(hi[0] + bias[0], hi[1] + bias[1],
                                       hi[2] + bias[2], hi[3] + bias[3]);
                *(float4*)&EW_buf[(size_t)(v0 + 1) * GATES + col0] = o;
            }
        }
    }
}

__global__ void pack_wh(const float* __restrict__ W) {
    int idx = blockIdx.x * 256 + threadIdx.x;
    if (idx < HIDDEN * GATES) {
        int c = idx % GATES;
        int k = idx / GATES;
        int g = c & 3, hh = c >> 2;
        Whp_buf[idx] = W[(size_t)(EMBED + k) * GATES + g * HIDDEN + hh];
    }
}

// ---------------------------------------------------------------------------
// Persistent LSTM scan. 144 blocks = 8 M-tiles x 18 N-tiles (BM=128, BN=68).
// Whp slice resident in smem; h tile double-buffered; ids preloaded.
// Per-M-tile 18-block barrier between steps (fully atomic publishes).
// ---------------------------------------------------------------------------
__global__ __launch_bounds__(256, 1) void lstm_persist(const int* __restrict__ ids) {
    extern __shared__ float smem_dyn[];
    float* Bsr  = smem_dyn;                       // [300][68]
    float* As   = smem_dyn + SM_B;                // [2][BK][ASTRIDE]
    int*   idsS = (int*)(smem_dyn + SM_B + SM_A); // [128][120]
    float* exch = smem_dyn + SM_B + SM_A + SM_IDS;// [4][128]

    const int tid = threadIdx.x;
    const int tx = tid & 15, ty = tid >> 4;
    const int mt = blockIdx.x % MT, nt = blockIdx.x / MT;
    const int rowBase = mt * BM;
    const int colBase = nt * BN;
    const int col0 = colBase + tx * 4;
    const int hh = col0 >> 2;
    const bool mainValid = (col0 < GATES);
    const int pe = 2 * (tid & 63);     // extra-acc row pair
    const int je = tid >> 6;           // extra-acc col 64+je
    const bool extraValid = (colBase + 67 < GATES);
    const int hhe = (colBase + 64) >> 2;

    // Resident B slice
    for (int idx = tid; idx < HIDDEN * BN; idx += 256) {
        int k = idx / BN, c = idx % BN;
        int col = colBase + c;
        Bsr[idx] = (col < GATES) ? Whp_buf[(size_t)k * GATES + col] : 0.f;
    }
    // ids for this block's 128 rows, all 120 steps
    for (int idx = tid; idx < BM * SEQ; idx += 256)
        idsS[idx] = ids[(size_t)(rowBase + idx / SEQ) * SEQ + (idx % SEQ)];
    __syncthreads();

    for (int t = 0; t < SEQ; t++) {
        u64 acc2[4][4];
        #pragma unroll
        for (int i = 0; i < 4; i++)
            #pragma unroll
            for (int j = 0; j < 4; j++) acc2[i][j] = 0ull;
        u64 acce = 0ull;

        if (t > 0) {
            const float* hprev = &Hall_buf[(size_t)(t - 1) * BATCH * HIDDEN + (size_t)rowBase * HIDDEN];
            float stage[15];

            #pragma unroll
            for (int j = 0; j < 15; j++) {
                int idx = tid + j * 256;
                int r = idx / BK, k = idx % BK;
                stage[j] = hprev[(size_t)r * HIDDEN + k];
            }
            #pragma unroll
            for (int j = 0; j < 15; j++) {
                int idx = tid + j * 256;
                int r = idx / BK, k = idx % BK;
                As[k * ASTRIDE + r] = stage[j];
            }
            __syncthreads();

            for (int c = 0; c < HIDDEN / BK; c++) {
                int kk = c * BK;
                if (c < HIDDEN / BK - 1) {
                    #pragma unroll
                    for (int j = 0; j < 15; j++) {
                        int idx = tid + j * 256;
                        int r = idx / BK, k = idx % BK;
                        stage[j] = hprev[(size_t)r * HIDDEN + kk + BK + k];
                    }
                }
                const float* Acur = &As[(c & 1) * BK * ASTRIDE];
                #pragma unroll 6
                for (int k = 0; k < BK; k++) {
                    ulonglong2 A0 = *(const ulonglong2*)&Acur[k * ASTRIDE + ty * 8];
                    ulonglong2 A1 = *(const ulonglong2*)&Acur[k * ASTRIDE + ty * 8 + 4];
                    float4 b4 = *(const float4*)&Bsr[(kk + k) * BN + tx * 4];
                    float be = Bsr[(kk + k) * BN + 64 + je];
                    u64 ae = *(const u64*)&Acur[k * ASTRIDE + pe];
                    u64 bd0 = pack2(b4.x, b4.x);
                    u64 bd1 = pack2(b4.y, b4.y);
                    u64 bd2 = pack2(b4.z, b4.z);
                    u64 bd3 = pack2(b4.w, b4.w);
                    u64 bde = pack2(be, be);
                    u64 ap0 = A0.x, ap1 = A0.y, ap2 = A1.x, ap3 = A1.y;
                    acc2[0][0] = ffma2(ap0, bd0, acc2[0][0]);
                    acc2[0][1] = ffma2(ap0, bd1, acc2[0][1]);
                    acc2[0][2] = ffma2(ap0, bd2, acc2[0][2]);
                    acc2[0][3] = ffma2(ap0, bd3, acc2[0][3]);
                    acc2[1][0] = ffma2(ap1, bd0, acc2[1][0]);
                    acc2[1][1] = ffma2(ap1, bd1, acc2[1][1]);
                    acc2[1][2] = ffma2(ap1, bd2, acc2[1][2]);
                    acc2[1][3] = ffma2(ap1, bd3, acc2[1][3]);
                    acc2[2][0] = ffma2(ap2, bd0, acc2[2][0]);
                    acc2[2][1] = ffma2(ap2, bd1, acc2[2][1]);
                    acc2[2][2] = ffma2(ap2, bd2, acc2[2][2]);
                    acc2[2][3] = ffma2(ap2, bd3, acc2[2][3]);
                    acc2[3][0] = ffma2(ap3, bd0, acc2[3][0]);
                    acc2[3][1] = ffma2(ap3, bd1, acc2[3][1]);
                    acc2[3][2] = ffma2(ap3, bd2, acc2[3][2]);
                    acc2[3][3] = ffma2(ap3, bd3, acc2[3][3]);
                    acce = ffma2(ae, bde, acce);
                }
                if (c < HIDDEN / BK - 1) {
                    float* Anext = &As[((c + 1) & 1) * BK * ASTRIDE];
                    #pragma unroll
                    for (int j = 0; j < 15; j++) {
                        int idx = tid + j * 256;
                        int r = idx / BK, k = idx % BK;
                        Anext[k * ASTRIDE + r] = stage[j];
                    }
                }
                __syncthreads();
            }
        }

        // publish extra-col partials
        {
            float lo, hi;
            unpack2(acce, lo, hi);
            exch[je * BM + pe] = lo;
            exch[je * BM + pe + 1] = hi;
        }

        // main epilogue: cols 0..63 of tile (full gate groups per thread)
        if (mainValid) {
            #pragma unroll
            for (int rp = 0; rp < 4; rp++) {
                float z0[4], z1[4];
                #pragma unroll
                for (int j = 0; j < 4; j++) unpack2(acc2[rp][j], z0[j], z1[j]);
                #pragma unroll
                for (int half = 0; half < 2; half++) {
                    float* z = half ? z1 : z0;
                    int lr = ty * 8 + rp * 2 + half;
                    int b = rowBase + lr;
                    int id = idsS[lr * SEQ + t];
                    float4 ew = *(const float4*)&EW_buf[(size_t)id * GATES + col0];
                    float zi = z[0] + ew.x;
                    float zj = z[1] + ew.y;
                    float zf = z[2] + ew.z;
                    float zo = z[3] + ew.w;
                    float cprev = (t == 0) ? 0.f : C_buf[b * HIDDEN + hh];
                    float cn = cprev * sigf(zf + 1.0f) + sigf(zi) * tanhf(zj);
                    float hn = tanhf(cn) * sigf(zo);
                    C_buf[b * HIDDEN + hh] = cn;
                    Hall_buf[((size_t)t * BATCH + b) * HIDDEN + hh] = hn;
                }
            }
        }

        __syncthreads();

        // extra epilogue: the 4 leftover cols = one gate group (unit hhe)
        if (tid < BM && extraValid) {
            int b = rowBase + tid;
            int id = idsS[tid * SEQ + t];
            float4 ew = *(const float4*)&EW_buf[(size_t)id * GATES + colBase + 64];
            float zi = exch[0 * BM + tid] + ew.x;
            float zj = exch[1 * BM + tid] + ew.y;
            float zf = exch[2 * BM + tid] + ew.z;
            float zo = exch[3 * BM + tid] + ew.w;
            float cprev = (t == 0) ? 0.f : C_buf[b * HIDDEN + hhe];
            float cn = cprev * sigf(zf + 1.0f) + sigf(zi) * tanhf(zj);
            float hn = tanhf(cn) * sigf(zo);
            C_buf[b * HIDDEN + hhe] = cn;
            Hall_buf[((size_t)t * BATCH + b) * HIDDEN + hhe] = hn;
        }

        // per-M-tile barrier: only the 18 blocks sharing mt must sync
        if (t < SEQ - 1) {
            __threadfence();
            __syncthreads();
            if (tid == 0) {
                unsigned gen = ld_volatile_u32(&bar_gen[mt]);
                if (atomicAdd(&bar_arrive[mt], 1u) == NT - 1) {
                    atomicExch(&bar_arrive[mt], 0u);
                    __threadfence();
                    atomicExch(&bar_gen[mt], gen + 1);
                } else {
                    int spins = 0;
                    while (ld_volatile_u32(&bar_gen[mt]) == gen) {
                        if (++spins > 16) __nanosleep(128);
                    }
                }
                __threadfence();
            }
            __syncthreads();
        }
    }
}

// ---------------------------------------------------------------------------
// out[row][c] = Hall[row] @ U + b2. 128 rows/block, f32x2 accum, float4 staging.
// ---------------------------------------------------------------------------
__global__ __launch_bounds__(PROJ_ROWS) void proj_kernel(const float* __restrict__ U,
                                                         const float* __restrict__ b2,
                                                         float* __restrict__ out) {
    extern __shared__ float psm[];
    float* Hs   = psm;                              // [128][308]
    float* Ut   = psm + PROJ_ROWS * HSTRIDE;        // [5][300]
    float* outS = Ut + HIDDEN * NCLASS;             // [128*5]
    float* b2s  = outS + PROJ_ROWS * NCLASS;

    const int tid = threadIdx.x;
    size_t rowBase = (size_t)blockIdx.x * PROJ_ROWS;
    const float* src = &Hall_buf[rowBase * HIDDEN];

    for (int i = tid; i < PROJ_ROWS * HIDDEN / 4; i += PROJ_ROWS) {
        float4 v = *(const float4*)&src[i * 4];
        int r = (i * 4) / HIDDEN, hh = (i * 4) % HIDDEN;
        *(float4*)&Hs[r * HSTRIDE + hh] = v;
    }
    for (int i = tid; i < HIDDEN * NCLASS; i += PROJ_ROWS) {
        int c = i / HIDDEN, hh = i % HIDDEN;
        Ut[i] = U[hh * NCLASS + c];
    }
    if (tid < NCLASS) b2s[tid] = b2[tid];
    __syncthreads();

    u64 acc[NCLASS];
    #pragma unroll
    for (int c = 0; c < NCLASS; c++) acc[c] = 0ull;

    const float* hrow = &Hs[tid * HSTRIDE];
    #pragma unroll 5
    for (int i = 0; i < HIDDEN / 4; i++) {
        ulonglong2 h2 = *(const ulonglong2*)&hrow[i * 4];
        #pragma unroll
        for (int c = 0; c < NCLASS; c++) {
            ulonglong2 u2 = *(const ulonglong2*)&Ut[c * HIDDEN + i * 4];
            acc[c] = ffma2(h2.x, u2.x, acc[c]);
            acc[c] = ffma2(h2.y, u2.y, acc[c]);
        }
    }
    #pragma unroll
    for (int c = 0; c < NCLASS; c++) {
        float lo, hi;
        unpack2(acc[c], lo, hi);
        outS[tid * NCLASS + c] = lo + hi + b2s[c];
    }
    __syncthreads();
    for (int i = tid; i < PROJ_ROWS * NCLASS; i += PROJ_ROWS)
        out[rowBase * NCLASS + i] = outS[i];
}

// ---------------------------------------------------------------------------
extern "C" void kernel_launch(void* const* d_in, const int* in_sizes, int n_in,
                              void* d_out, int out_size) {
    const int*   ids = (const int*)d_in[0];     // (1024,120,1) int32
    const float* emb = (const float*)d_in[1];   // (50000,50)
    const float* W   = (const float*)d_in[2];   // (350,1200)
    const float* bl  = (const float*)d_in[3];   // (1200)
    const float* U   = (const float*)d_in[4];   // (300,5)
    const float* b2  = (const float*)d_in[5];   // (5)
    float* out = (float*)d_out;                 // (120,1024,5)

    cudaFuncSetAttribute(lstm_persist,
                         cudaFuncAttributeMaxDynamicSharedMemorySize, SMEM_BYTES);
    cudaFuncSetAttribute(proj_kernel,
                         cudaFuncAttributeMaxDynamicSharedMemorySize, PROJ_SMEM);

    dim3 ewgrid((GATES + 63) / 64, (VOCAB + 63) / 64);
    ew_kernel<<<ewgrid, 256>>>(emb, W, bl);
    pack_wh<<<(HIDDEN * GATES + 255) / 256, 256>>>(W);

    lstm_persist<<<NBLK, 256, SMEM_BYTES>>>(ids);

    proj_kernel<<<(SEQ * BATCH) / PROJ_ROWS, PROJ_ROWS, PROJ_SMEM>>>(U, b2, out);
}